// round 1
// baseline (speedup 1.0000x reference)
#include <cuda_runtime.h>

#define TT   1000
#define NCH  4096

// scratch (no cudaMalloc allowed)
__device__ float g_seq[NCH * TT];     // LSTM input, [chain][t], 16 MB
__device__ float g_feat[NCH * 32];    // [chain][ h_fwd(16) | h_bwd(16) ]

__device__ __forceinline__ float gelu_exact(float v) {
    return 0.5f * v * (1.0f + erff(v * 0.70710678118654752f));
}

__device__ __forceinline__ float fast_sig(float x) {
    // 1/(1+e^-x); exp overflow -> inf -> rcp -> 0 (correct limit)
    return __fdividef(1.0f, 1.0f + __expf(-x));
}

__device__ __forceinline__ float fast_tanh(float x) {
    float e = __expf(-2.0f * fabsf(x));          // in (0,1], no overflow
    float r = __fdividef(1.0f - e, 1.0f + e);
    return copysignf(r, x);
}

// ---------------------------------------------------------------------------
// Kernel 1: fused depthwise-conv(5,pad2)+BN+GELU  x2.  One block per (b,c) row.
// ---------------------------------------------------------------------------
__global__ void __launch_bounds__(256) prep_kernel(
    const float* __restrict__ x,
    const float* __restrict__ c1w, const float* __restrict__ c1b,
    const float* __restrict__ b1g, const float* __restrict__ b1b,
    const float* __restrict__ b1m, const float* __restrict__ b1v,
    const float* __restrict__ c2w, const float* __restrict__ c2b,
    const float* __restrict__ b2g, const float* __restrict__ b2b,
    const float* __restrict__ b2m, const float* __restrict__ b2v)
{
    __shared__ float xs[TT + 4];
    __shared__ float ys[TT + 4];

    const int chain = blockIdx.x;          // b*64 + c
    const int ch    = chain & 63;
    const int tid   = threadIdx.x;

    if (tid < 2) {
        xs[tid] = 0.0f; xs[TT + 2 + tid] = 0.0f;
        ys[tid] = 0.0f; ys[TT + 2 + tid] = 0.0f;
    }
    const float* xr = x + (size_t)chain * TT;
    for (int t = tid; t < TT; t += 256) xs[t + 2] = xr[t];

    const float w0 = c1w[ch * 5 + 0], w1 = c1w[ch * 5 + 1], w2 = c1w[ch * 5 + 2],
                w3 = c1w[ch * 5 + 3], w4 = c1w[ch * 5 + 4];
    const float s1 = b1g[ch] * rsqrtf(b1v[ch] + 1e-5f);
    const float d1 = (c1b[ch] - b1m[ch]) * s1 + b1b[ch];

    __syncthreads();
    for (int t = tid; t < TT; t += 256) {
        float a = xs[t] * w0;
        a = fmaf(xs[t + 1], w1, a);
        a = fmaf(xs[t + 2], w2, a);
        a = fmaf(xs[t + 3], w3, a);
        a = fmaf(xs[t + 4], w4, a);
        ys[t + 2] = gelu_exact(fmaf(a, s1, d1));
    }

    const float u0 = c2w[ch * 5 + 0], u1 = c2w[ch * 5 + 1], u2 = c2w[ch * 5 + 2],
                u3 = c2w[ch * 5 + 3], u4 = c2w[ch * 5 + 4];
    const float s2 = b2g[ch] * rsqrtf(b2v[ch] + 1e-5f);
    const float d2 = (c2b[ch] - b2m[ch]) * s2 + b2b[ch];

    __syncthreads();
    float* outr = g_seq + (size_t)chain * TT;
    for (int t = tid; t < TT; t += 256) {
        float a = ys[t] * u0;
        a = fmaf(ys[t + 1], u1, a);
        a = fmaf(ys[t + 2], u2, a);
        a = fmaf(ys[t + 3], u3, a);
        a = fmaf(ys[t + 4], u4, a);
        outr[t] = gelu_exact(fmaf(a, s2, d2));
    }
}

// ---------------------------------------------------------------------------
// Kernel 2: LSTM. 16 lanes per chain (one per hidden unit), h via shfl.
// gchain in [0,4096) = forward, [4096,8192) = backward on reversed sequence.
// ---------------------------------------------------------------------------
__global__ void __launch_bounds__(128) lstm_kernel(
    const float* __restrict__ wihf, const float* __restrict__ whhf,
    const float* __restrict__ bihf, const float* __restrict__ bhhf,
    const float* __restrict__ wihr, const float* __restrict__ whhr,
    const float* __restrict__ bihr, const float* __restrict__ bhhr)
{
    const int tid = threadIdx.x;
    const int j   = tid & 15;                       // hidden unit
    const int g   = blockIdx.x * 8 + (tid >> 4);    // 0..8191
    const bool bwd = (g >= NCH);
    const int chain = bwd ? g - NCH : g;

    const float* wih = bwd ? wihr : wihf;
    const float* whh = bwd ? whhr : whhf;
    const float* bih = bwd ? bihr : bihf;
    const float* bhh = bwd ? bhhr : bhhf;

    float W[4][16];   // W_hh rows for gates i,f,g,o at hidden unit j
    float wi[4], bb[4];
#pragma unroll
    for (int k = 0; k < 4; k++) {
        const int row = k * 16 + j;
        wi[k] = wih[row];
        bb[k] = bih[row] + bhh[row];
#pragma unroll
        for (int i = 0; i < 16; i++) W[k][i] = whh[row * 16 + i];
    }

    const float* seq = g_seq + (size_t)chain * TT;
    float h = 0.0f, c = 0.0f;

    for (int t0 = 0; t0 < TT; t0 += 16) {
        const int steps = (TT - t0) < 16 ? (TT - t0) : 16;
        const int tloc  = t0 + j;
        float xv = 0.0f;
        if (tloc < TT) xv = seq[bwd ? (TT - 1 - tloc) : tloc];   // coalesced 64B/chain

        for (int i = 0; i < steps; i++) {
            const float xt = __shfl_sync(0xffffffffu, xv, i, 16);
            float g0 = fmaf(xt, wi[0], bb[0]);
            float g1 = fmaf(xt, wi[1], bb[1]);
            float g2 = fmaf(xt, wi[2], bb[2]);
            float g3 = fmaf(xt, wi[3], bb[3]);
#pragma unroll
            for (int ii = 0; ii < 16; ii++) {
                const float hv = __shfl_sync(0xffffffffu, h, ii, 16);
                g0 = fmaf(hv, W[0][ii], g0);
                g1 = fmaf(hv, W[1][ii], g1);
                g2 = fmaf(hv, W[2][ii], g2);
                g3 = fmaf(hv, W[3][ii], g3);
            }
            const float ig = fast_sig(g0);
            const float fg = fast_sig(g1);
            const float gg = fast_tanh(g2);
            const float og = fast_sig(g3);
            c = fmaf(fg, c, ig * gg);
            h = og * fast_tanh(c);
        }
    }

    g_feat[chain * 32 + (bwd ? 16 : 0) + j] = h;
}

// ---------------------------------------------------------------------------
// Kernel 3: out[n,e] = feat[n,:] . lin_w[e,:] + lin_b[e]
// ---------------------------------------------------------------------------
__global__ void __launch_bounds__(256) linear_kernel(
    const float* __restrict__ lw, const float* __restrict__ lb,
    float* __restrict__ out)
{
    const int idx = blockIdx.x * 256 + threadIdx.x;    // 131072 total
    const int n = idx >> 5;
    const int e = idx & 31;
    const float* f = g_feat + n * 32;
    const float* w = lw + e * 32;
    float acc = lb[e];
#pragma unroll
    for (int k = 0; k < 32; k++) acc = fmaf(f[k], w[k], acc);
    out[idx] = acc;
}

// ---------------------------------------------------------------------------
extern "C" void kernel_launch(void* const* d_in, const int* in_sizes, int n_in,
                              void* d_out, int out_size)
{
    const float* x      = (const float*)d_in[0];
    const float* c1w    = (const float*)d_in[1];
    const float* c1b    = (const float*)d_in[2];
    const float* b1g    = (const float*)d_in[3];
    const float* b1b    = (const float*)d_in[4];
    const float* b1m    = (const float*)d_in[5];
    const float* b1v    = (const float*)d_in[6];
    const float* c2w    = (const float*)d_in[7];
    const float* c2b    = (const float*)d_in[8];
    const float* b2g    = (const float*)d_in[9];
    const float* b2b    = (const float*)d_in[10];
    const float* b2m    = (const float*)d_in[11];
    const float* b2v    = (const float*)d_in[12];
    const float* wihf   = (const float*)d_in[13];
    const float* whhf   = (const float*)d_in[14];
    const float* bihf   = (const float*)d_in[15];
    const float* bhhf   = (const float*)d_in[16];
    const float* wihr   = (const float*)d_in[17];
    const float* whhr   = (const float*)d_in[18];
    const float* bihr   = (const float*)d_in[19];
    const float* bhhr   = (const float*)d_in[20];
    const float* lw     = (const float*)d_in[21];
    const float* lb     = (const float*)d_in[22];
    float* out = (float*)d_out;

    prep_kernel<<<NCH, 256>>>(x, c1w, c1b, b1g, b1b, b1m, b1v,
                              c2w, c2b, b2g, b2b, b2m, b2v);
    lstm_kernel<<<(2 * NCH) / 8, 128>>>(wihf, whhf, bihf, bhhf,
                                        wihr, whhr, bihr, bhhr);
    linear_kernel<<<(NCH * 32) / 256, 256>>>(lw, lb, out);
}